// round 1
// baseline (speedup 1.0000x reference)
#include <cuda_runtime.h>
#include <math.h>
#include <stdint.h>

#define BDIM 4
#define NSEQ 1024
#define DMODEL 1024
#define HEADS 16
#define DHEAD 64
#define INNER 1024
#define THREE_INNER 3072

// Scratch (no allocations allowed) --------------------------------------------
__device__ float g_qkv[BDIM * NSEQ * THREE_INNER];   // [B*N, 3*INNER]
__device__ float g_attn[BDIM * NSEQ * INNER];        // [B*N, INNER]

// ---------------------------------------------------------------------------
// SGEMM: C[M,N] = A[M,K] @ B[K,N] (+ bias[n])
// 128x128 tile, BK=16, 256 threads, 8x8 per-thread microtile.
// As stored k-major with pitch 129 (odd) -> conflict-free transposed STS,
// broadcast LDS in the FFMA loop. Bs pitch 132 (16B-aligned rows for float4).
// Requires M%128==0, N%128==0, K%16==0.
// ---------------------------------------------------------------------------
template <bool HAS_BIAS>
__global__ void __launch_bounds__(256) sgemm_kernel(
    const float* __restrict__ A, const float* __restrict__ B,
    const float* __restrict__ bias, float* __restrict__ C,
    int M, int N, int K)
{
    constexpr int PA = 129;
    constexpr int PB = 132;
    __shared__ float As[16 * PA];
    __shared__ float Bs[16 * PB];

    const int tid = threadIdx.x;
    const int tx = tid & 15;        // 0..15 -> C cols tx*8..tx*8+7
    const int ty = tid >> 4;        // 0..15 -> C rows ty*8..ty*8+7
    const int m0 = blockIdx.y * 128;
    const int n0 = blockIdx.x * 128;

    float acc[8][8];
#pragma unroll
    for (int i = 0; i < 8; ++i)
#pragma unroll
        for (int j = 0; j < 8; ++j) acc[i][j] = 0.0f;

    for (int kt = 0; kt < K; kt += 16) {
        // Load A tile [128 rows x 16 k] -> As[k][m]
#pragma unroll
        for (int p = 0; p < 2; ++p) {
            int idx = tid + p * 256;          // 0..511
            int r = idx >> 2;                 // 0..127
            int kq = (idx & 3) * 4;           // 0,4,8,12
            float4 v = *(const float4*)(A + (size_t)(m0 + r) * K + kt + kq);
            As[(kq + 0) * PA + r] = v.x;
            As[(kq + 1) * PA + r] = v.y;
            As[(kq + 2) * PA + r] = v.z;
            As[(kq + 3) * PA + r] = v.w;
        }
        // Load B tile [16 k x 128 n] -> Bs[k][n]
#pragma unroll
        for (int p = 0; p < 2; ++p) {
            int idx = tid + p * 256;
            int kk = idx >> 5;                // 0..15
            int nq = (idx & 31) * 4;          // 0..124
            float4 v = *(const float4*)(B + (size_t)(kt + kk) * N + n0 + nq);
            *(float4*)(Bs + kk * PB + nq) = v;
        }
        __syncthreads();

#pragma unroll
        for (int k = 0; k < 16; ++k) {
            float a[8], b[8];
#pragma unroll
            for (int i = 0; i < 8; ++i) a[i] = As[k * PA + ty * 8 + i];
#pragma unroll
            for (int j = 0; j < 8; ++j) b[j] = Bs[k * PB + tx * 8 + j];
#pragma unroll
            for (int i = 0; i < 8; ++i)
#pragma unroll
                for (int j = 0; j < 8; ++j) acc[i][j] = fmaf(a[i], b[j], acc[i][j]);
        }
        __syncthreads();
    }

    // Epilogue (vectorized over j)
#pragma unroll
    for (int i = 0; i < 8; ++i) {
        size_t row = (size_t)(m0 + ty * 8 + i) * N + n0 + tx * 8;
#pragma unroll
        for (int jq = 0; jq < 2; ++jq) {
            float4 v;
            v.x = acc[i][jq * 4 + 0];
            v.y = acc[i][jq * 4 + 1];
            v.z = acc[i][jq * 4 + 2];
            v.w = acc[i][jq * 4 + 3];
            if (HAS_BIAS) {
                const float4 bb = *(const float4*)(bias + n0 + tx * 8 + jq * 4);
                v.x += bb.x; v.y += bb.y; v.z += bb.z; v.w += bb.w;
            }
            *(float4*)(C + row + jq * 4) = v;
        }
    }
}

// ---------------------------------------------------------------------------
// Flash-style masked attention.
// grid: (N/64, B*H). block: 256 threads (16x16), each owns 4x4 of S and O.
// Q,K stored d-major (pitch 65) in smem; V,P stored j-major (pitch 65).
// Online softmax state (m,l) replicated in registers across each 16-lane
// row group; reductions via shfl_xor 1/2/4/8.
// Key masking: s -> -1e30 with explicit p=0 guard; query rows with mask==0
// are zeroed in the epilogue (reference: valid row <=> mask_i==1).
// ---------------------------------------------------------------------------
__global__ void __launch_bounds__(256) attn_kernel(
    const float* __restrict__ qkv, const float* __restrict__ mask,
    float* __restrict__ out)
{
    constexpr int P = 65;
    extern __shared__ float sm[];
    float* QsT = sm;                  // [64 d][P]  QsT[d*P + i]
    float* KsT = QsT + 64 * P;        // [64 d][P]  KsT[d*P + j]
    float* Vs  = KsT + 64 * P;        // [64 j][P]  Vs[j*P + c]
    float* PsT = Vs  + 64 * P;        // [64 j][P]  PsT[j*P + i]
    float* mk  = PsT + 64 * P;        // [64] key mask

    const int bh = blockIdx.y;
    const int b = bh / HEADS;
    const int h = bh % HEADS;
    const int q0 = blockIdx.x * 64;
    const int tid = threadIdx.x;
    const int tx = tid & 15;          // S cols / O cols: tx*4..+3
    const int ty = tid >> 4;          // S rows / O rows: ty*4..+3
    const float scale = 0.125f;       // 64^-0.5

    const float* qbase = qkv + (size_t)b * NSEQ * THREE_INNER + h * DHEAD;
    const float* kbase = qbase + INNER;
    const float* vbase = qbase + 2 * INNER;

    // Load Q tile transposed: QsT[d][i]
#pragma unroll
    for (int p = 0; p < 4; ++p) {
        int idx = tid + p * 256;          // 0..1023
        int i = idx >> 4;                 // 0..63
        int d = (idx & 15) * 4;           // 0..60
        float4 v = *(const float4*)(qbase + (size_t)(q0 + i) * THREE_INNER + d);
        QsT[(d + 0) * P + i] = v.x;
        QsT[(d + 1) * P + i] = v.y;
        QsT[(d + 2) * P + i] = v.z;
        QsT[(d + 3) * P + i] = v.w;
    }

    float O[4][4];
    float mrow[4], lrow[4];
#pragma unroll
    for (int a = 0; a < 4; ++a) {
        mrow[a] = -1e30f;
        lrow[a] = 0.0f;
#pragma unroll
        for (int c = 0; c < 4; ++c) O[a][c] = 0.0f;
    }

    for (int kt = 0; kt < NSEQ; kt += 64) {
        __syncthreads();  // prev PV done (Vs/PsT) + first-iter Q writes visible
        // Load K tile transposed + V tile + key mask
#pragma unroll
        for (int p = 0; p < 4; ++p) {
            int idx = tid + p * 256;
            int j = idx >> 4;
            int d = (idx & 15) * 4;
            float4 kv = *(const float4*)(kbase + (size_t)(kt + j) * THREE_INNER + d);
            KsT[(d + 0) * P + j] = kv.x;
            KsT[(d + 1) * P + j] = kv.y;
            KsT[(d + 2) * P + j] = kv.z;
            KsT[(d + 3) * P + j] = kv.w;
            float4 vv = *(const float4*)(vbase + (size_t)(kt + j) * THREE_INNER + d);
            Vs[j * P + d + 0] = vv.x;
            Vs[j * P + d + 1] = vv.y;
            Vs[j * P + d + 2] = vv.z;
            Vs[j * P + d + 3] = vv.w;
        }
        if (tid < 64) mk[tid] = mask[(size_t)b * NSEQ + kt + tid];
        __syncthreads();

        // S = Q @ K^T
        float s[4][4];
#pragma unroll
        for (int a = 0; a < 4; ++a)
#pragma unroll
            for (int j = 0; j < 4; ++j) s[a][j] = 0.0f;
#pragma unroll
        for (int d = 0; d < 64; ++d) {
            float qa[4], kb[4];
#pragma unroll
            for (int a = 0; a < 4; ++a) qa[a] = QsT[d * P + ty * 4 + a];
#pragma unroll
            for (int j = 0; j < 4; ++j) kb[j] = KsT[d * P + tx * 4 + j];
#pragma unroll
            for (int a = 0; a < 4; ++a)
#pragma unroll
                for (int j = 0; j < 4; ++j) s[a][j] = fmaf(qa[a], kb[j], s[a][j]);
        }

        // Scale + key mask
        float mkj[4];
#pragma unroll
        for (int j = 0; j < 4; ++j) mkj[j] = mk[tx * 4 + j];
#pragma unroll
        for (int a = 0; a < 4; ++a)
#pragma unroll
            for (int j = 0; j < 4; ++j)
                s[a][j] = (mkj[j] != 0.0f) ? s[a][j] * scale : -1e30f;

        // Online softmax update (replicated across 16-lane row group)
        float corr[4];
#pragma unroll
        for (int a = 0; a < 4; ++a) {
            float rmax = fmaxf(fmaxf(s[a][0], s[a][1]), fmaxf(s[a][2], s[a][3]));
#pragma unroll
            for (int m = 8; m >= 1; m >>= 1)
                rmax = fmaxf(rmax, __shfl_xor_sync(0xffffffffu, rmax, m));
            float mnew = fmaxf(mrow[a], rmax);
            corr[a] = expf(mrow[a] - mnew);
            float rs = 0.0f;
#pragma unroll
            for (int j = 0; j < 4; ++j) {
                float pj = (s[a][j] > -1e29f) ? expf(s[a][j] - mnew) : 0.0f;
                s[a][j] = pj;
                rs += pj;
            }
#pragma unroll
            for (int m = 8; m >= 1; m >>= 1)
                rs += __shfl_xor_sync(0xffffffffu, rs, m);
            lrow[a] = lrow[a] * corr[a] + rs;
            mrow[a] = mnew;
        }

        // Stage P transposed: PsT[j][i]
#pragma unroll
        for (int a = 0; a < 4; ++a)
#pragma unroll
            for (int j = 0; j < 4; ++j)
                PsT[(tx * 4 + j) * P + ty * 4 + a] = s[a][j];

        // Rescale O
#pragma unroll
        for (int a = 0; a < 4; ++a)
#pragma unroll
            for (int c = 0; c < 4; ++c) O[a][c] *= corr[a];

        __syncthreads();

        // O += P @ V
#pragma unroll
        for (int j = 0; j < 64; ++j) {
            float pa[4], vb[4];
#pragma unroll
            for (int a = 0; a < 4; ++a) pa[a] = PsT[j * P + ty * 4 + a];
#pragma unroll
            for (int c = 0; c < 4; ++c) vb[c] = Vs[j * P + tx * 4 + c];
#pragma unroll
            for (int a = 0; a < 4; ++a)
#pragma unroll
                for (int c = 0; c < 4; ++c) O[a][c] = fmaf(pa[a], vb[c], O[a][c]);
        }
    }

    // Epilogue: normalize, zero invalid query rows, write [B,N,H*DH]
#pragma unroll
    for (int a = 0; a < 4; ++a) {
        int i = ty * 4 + a;
        float mq = mask[(size_t)b * NSEQ + q0 + i];
        float inv = (mq != 0.0f) ? (1.0f / lrow[a]) : 0.0f;
        float4 v;
        v.x = O[a][0] * inv;
        v.y = O[a][1] * inv;
        v.z = O[a][2] * inv;
        v.w = O[a][3] * inv;
        *(float4*)(out + (size_t)(b * NSEQ + q0 + i) * INNER + h * DHEAD + tx * 4) = v;
    }
}

// ---------------------------------------------------------------------------
extern "C" void kernel_launch(void* const* d_in, const int* in_sizes, int n_in,
                              void* d_out, int out_size)
{
    (void)in_sizes; (void)n_in; (void)out_size;
    const float* x     = (const float*)d_in[0];  // [B,N,D]
    const float* mask  = (const float*)d_in[1];  // [B,N]
    const float* w_qkv = (const float*)d_in[2];  // [D, 3*INNER]
    const float* w_out = (const float*)d_in[3];  // [INNER, D]
    const float* b_out = (const float*)d_in[4];  // [D]
    float* out = (float*)d_out;                  // [B,N,D]

    void* p_qkv = nullptr;
    void* p_attn = nullptr;
    cudaGetSymbolAddress(&p_qkv, g_qkv);
    cudaGetSymbolAddress(&p_attn, g_attn);
    float* qkv = (float*)p_qkv;
    float* attn = (float*)p_attn;

    // 1) QKV = X @ Wqkv : [4096,1024] x [1024,3072]
    {
        dim3 grid(THREE_INNER / 128, (BDIM * NSEQ) / 128);
        sgemm_kernel<false><<<grid, 256>>>(x, w_qkv, nullptr, qkv,
                                           BDIM * NSEQ, THREE_INNER, DMODEL);
    }

    // 2) Attention
    {
        const int smem_bytes = (4 * 64 * 65 + 64) * sizeof(float);  // ~66.8 KB
        cudaFuncSetAttribute(attn_kernel,
                             cudaFuncAttributeMaxDynamicSharedMemorySize,
                             smem_bytes);
        dim3 grid(NSEQ / 64, BDIM * HEADS);
        attn_kernel<<<grid, 256, smem_bytes>>>(qkv, mask, attn);
    }

    // 3) Out = Attn @ Wout + b : [4096,1024] x [1024,1024]
    {
        dim3 grid(DMODEL / 128, (BDIM * NSEQ) / 128);
        sgemm_kernel<true><<<grid, 256>>>(attn, w_out, b_out, out,
                                          BDIM * NSEQ, DMODEL, INNER);
    }
}

// round 2
// speedup vs baseline: 1.1674x; 1.1674x over previous
#include <cuda_runtime.h>
#include <math.h>
#include <stdint.h>

#define BDIM 4
#define NSEQ 1024
#define DMODEL 1024
#define HEADS 16
#define DHEAD 64
#define INNER 1024
#define THREE_INNER 3072

// Scratch (no allocations allowed) --------------------------------------------
__device__ float g_qkv[BDIM * NSEQ * THREE_INNER];   // [B*N, 3*INNER]
__device__ float g_attn[BDIM * NSEQ * INNER];        // [B*N, INNER]

// ---------------------------------------------------------------------------
// SGEMM v2: C[M,N] = A[M,K] @ B[K,N] (+ bias[n])
// 128x128 tile, BK=16, 256 threads, 8x8 microtile split into 2x2 blocks of
// 4x4 at rows {ty*4, 64+ty*4}, cols {tx*4, 64+tx*4} -> all fragment loads are
// conflict-free LDS.128. Double-buffered smem, register-staged prefetch,
// one __syncthreads per K-tile.
// Requires M%128==0, N%128==0, K%16==0.
// ---------------------------------------------------------------------------
template <bool HAS_BIAS>
__global__ void __launch_bounds__(256, 2) sgemm_kernel(
    const float* __restrict__ A, const float* __restrict__ B,
    const float* __restrict__ bias, float* __restrict__ C,
    int M, int N, int K)
{
    constexpr int PP = 132;                 // pitch (floats), divisible by 4
    __shared__ float As[2][16 * PP];
    __shared__ float Bs[2][16 * PP];

    const int tid = threadIdx.x;
    const int tx = tid & 15;
    const int ty = tid >> 4;
    const int m0 = blockIdx.y * 128;
    const int n0 = blockIdx.x * 128;

    // gmem load coordinates (2 float4 each for A and B)
    const int ar0 = tid >> 2;               // 0..63   (p=0)
    const int akq = (tid & 3) << 2;         // 0,4,8,12
    const int bk0 = tid >> 5;               // 0..7    (p=0)
    const int bnq = (tid & 31) << 2;        // 0..124

    float acc[8][8];
#pragma unroll
    for (int i = 0; i < 8; ++i)
#pragma unroll
        for (int j = 0; j < 8; ++j) acc[i][j] = 0.0f;

    float4 ra[2], rb[2];

    // prefetch tile kt=0
#pragma unroll
    for (int p = 0; p < 2; ++p) {
        ra[p] = *(const float4*)(A + (size_t)(m0 + ar0 + p * 64) * K + akq);
        rb[p] = *(const float4*)(B + (size_t)(bk0 + p * 8) * N + n0 + bnq);
    }
    // store tile 0 -> buf 0
#pragma unroll
    for (int p = 0; p < 2; ++p) {
        As[0][(akq + 0) * PP + ar0 + p * 64] = ra[p].x;
        As[0][(akq + 1) * PP + ar0 + p * 64] = ra[p].y;
        As[0][(akq + 2) * PP + ar0 + p * 64] = ra[p].z;
        As[0][(akq + 3) * PP + ar0 + p * 64] = ra[p].w;
        *(float4*)(Bs[0] + (bk0 + p * 8) * PP + bnq) = rb[p];
    }
    __syncthreads();

    int cur = 0;
    for (int kt = 16; kt <= K; kt += 16) {
        if (kt < K) {
#pragma unroll
            for (int p = 0; p < 2; ++p) {
                ra[p] = *(const float4*)(A + (size_t)(m0 + ar0 + p * 64) * K + kt + akq);
                rb[p] = *(const float4*)(B + (size_t)(kt + bk0 + p * 8) * N + n0 + bnq);
            }
        }

        const float* __restrict__ as = As[cur];
        const float* __restrict__ bs = Bs[cur];
#pragma unroll
        for (int k = 0; k < 16; ++k) {
            float a[8], b[8];
            *(float4*)&a[0] = *(const float4*)(as + k * PP + ty * 4);
            *(float4*)&a[4] = *(const float4*)(as + k * PP + 64 + ty * 4);
            *(float4*)&b[0] = *(const float4*)(bs + k * PP + tx * 4);
            *(float4*)&b[4] = *(const float4*)(bs + k * PP + 64 + tx * 4);
#pragma unroll
            for (int i = 0; i < 8; ++i)
#pragma unroll
                for (int j = 0; j < 8; ++j) acc[i][j] = fmaf(a[i], b[j], acc[i][j]);
        }

        if (kt < K) {
            int nb = cur ^ 1;
#pragma unroll
            for (int p = 0; p < 2; ++p) {
                As[nb][(akq + 0) * PP + ar0 + p * 64] = ra[p].x;
                As[nb][(akq + 1) * PP + ar0 + p * 64] = ra[p].y;
                As[nb][(akq + 2) * PP + ar0 + p * 64] = ra[p].z;
                As[nb][(akq + 3) * PP + ar0 + p * 64] = ra[p].w;
                *(float4*)(Bs[nb] + (bk0 + p * 8) * PP + bnq) = rb[p];
            }
            __syncthreads();
            cur = nb;
        }
    }

    // Epilogue
#pragma unroll
    for (int ih = 0; ih < 2; ++ih) {
#pragma unroll
        for (int i = 0; i < 4; ++i) {
            size_t row = (size_t)(m0 + ih * 64 + ty * 4 + i) * N;
#pragma unroll
            for (int jh = 0; jh < 2; ++jh) {
                int col = n0 + jh * 64 + tx * 4;
                float4 v;
                v.x = acc[ih * 4 + i][jh * 4 + 0];
                v.y = acc[ih * 4 + i][jh * 4 + 1];
                v.z = acc[ih * 4 + i][jh * 4 + 2];
                v.w = acc[ih * 4 + i][jh * 4 + 3];
                if (HAS_BIAS) {
                    const float4 bb = *(const float4*)(bias + col);
                    v.x += bb.x; v.y += bb.y; v.z += bb.z; v.w += bb.w;
                }
                *(float4*)(C + row + col) = v;
            }
        }
    }
}

// ---------------------------------------------------------------------------
// Flash-style masked attention (v2: vectorized smem, pitch 68, __expf).
// grid: (N/64, B*H). block: 256 threads (16x16), each owns 4x4 of S and O.
// ---------------------------------------------------------------------------
__global__ void __launch_bounds__(256) attn_kernel(
    const float* __restrict__ qkv, const float* __restrict__ mask,
    float* __restrict__ out)
{
    constexpr int P = 68;             // pitch (floats), divisible by 4
    extern __shared__ float sm[];
    float* QsT = sm;                  // [64 d][P]  QsT[d*P + i]
    float* KsT = QsT + 64 * P;        // [64 d][P]  KsT[d*P + j]
    float* Vs  = KsT + 64 * P;        // [64 j][P]  Vs[j*P + c]
    float* PsT = Vs  + 64 * P;        // [64 j][P]  PsT[j*P + i]
    float* mk  = PsT + 64 * P;        // [64] key mask

    const int bh = blockIdx.y;
    const int b = bh / HEADS;
    const int h = bh % HEADS;
    const int q0 = blockIdx.x * 64;
    const int tid = threadIdx.x;
    const int tx = tid & 15;
    const int ty = tid >> 4;
    const float scale = 0.125f;       // 64^-0.5

    const float* qbase = qkv + (size_t)b * NSEQ * THREE_INNER + h * DHEAD;
    const float* kbase = qbase + INNER;
    const float* vbase = qbase + 2 * INNER;

    // Load Q tile transposed: QsT[d][i]
#pragma unroll
    for (int p = 0; p < 4; ++p) {
        int idx = tid + p * 256;
        int i = idx >> 4;
        int d = (idx & 15) * 4;
        float4 v = *(const float4*)(qbase + (size_t)(q0 + i) * THREE_INNER + d);
        QsT[(d + 0) * P + i] = v.x;
        QsT[(d + 1) * P + i] = v.y;
        QsT[(d + 2) * P + i] = v.z;
        QsT[(d + 3) * P + i] = v.w;
    }

    float O[4][4];
    float mrow[4], lrow[4];
#pragma unroll
    for (int a = 0; a < 4; ++a) {
        mrow[a] = -1e30f;
        lrow[a] = 0.0f;
#pragma unroll
        for (int c = 0; c < 4; ++c) O[a][c] = 0.0f;
    }

    for (int kt = 0; kt < NSEQ; kt += 64) {
        __syncthreads();  // prev PV reads done; Q writes visible (first iter)
#pragma unroll
        for (int p = 0; p < 4; ++p) {
            int idx = tid + p * 256;
            int j = idx >> 4;
            int d = (idx & 15) * 4;
            float4 kv = *(const float4*)(kbase + (size_t)(kt + j) * THREE_INNER + d);
            KsT[(d + 0) * P + j] = kv.x;
            KsT[(d + 1) * P + j] = kv.y;
            KsT[(d + 2) * P + j] = kv.z;
            KsT[(d + 3) * P + j] = kv.w;
            float4 vv = *(const float4*)(vbase + (size_t)(kt + j) * THREE_INNER + d);
            *(float4*)(Vs + j * P + d) = vv;
        }
        if (tid < 64) mk[tid] = mask[(size_t)b * NSEQ + kt + tid];
        __syncthreads();

        // S = Q @ K^T
        float s[4][4];
#pragma unroll
        for (int a = 0; a < 4; ++a)
#pragma unroll
            for (int j = 0; j < 4; ++j) s[a][j] = 0.0f;
#pragma unroll
        for (int d = 0; d < 64; ++d) {
            float qa[4], kb[4];
            *(float4*)&qa[0] = *(const float4*)(QsT + d * P + ty * 4);
            *(float4*)&kb[0] = *(const float4*)(KsT + d * P + tx * 4);
#pragma unroll
            for (int a = 0; a < 4; ++a)
#pragma unroll
                for (int j = 0; j < 4; ++j) s[a][j] = fmaf(qa[a], kb[j], s[a][j]);
        }

        // Scale + key mask
        float mkj[4];
        *(float4*)&mkj[0] = *(const float4*)(mk + tx * 4);
#pragma unroll
        for (int a = 0; a < 4; ++a)
#pragma unroll
            for (int j = 0; j < 4; ++j)
                s[a][j] = (mkj[j] != 0.0f) ? s[a][j] * scale : -1e30f;

        // Online softmax update (replicated across 16-lane row group)
        float corr[4];
#pragma unroll
        for (int a = 0; a < 4; ++a) {
            float rmax = fmaxf(fmaxf(s[a][0], s[a][1]), fmaxf(s[a][2], s[a][3]));
#pragma unroll
            for (int m = 8; m >= 1; m >>= 1)
                rmax = fmaxf(rmax, __shfl_xor_sync(0xffffffffu, rmax, m));
            float mnew = fmaxf(mrow[a], rmax);
            corr[a] = __expf(mrow[a] - mnew);
            float rs = 0.0f;
#pragma unroll
            for (int j = 0; j < 4; ++j) {
                float pj = (s[a][j] > -1e29f) ? __expf(s[a][j] - mnew) : 0.0f;
                s[a][j] = pj;
                rs += pj;
            }
#pragma unroll
            for (int m = 8; m >= 1; m >>= 1)
                rs += __shfl_xor_sync(0xffffffffu, rs, m);
            lrow[a] = lrow[a] * corr[a] + rs;
            mrow[a] = mnew;
        }

        // Stage P transposed: PsT[j][i] (float4 along i)
#pragma unroll
        for (int j = 0; j < 4; ++j) {
            float4 v;
            v.x = s[0][j]; v.y = s[1][j]; v.z = s[2][j]; v.w = s[3][j];
            *(float4*)(PsT + (tx * 4 + j) * P + ty * 4) = v;
        }

        // Rescale O
#pragma unroll
        for (int a = 0; a < 4; ++a)
#pragma unroll
            for (int c = 0; c < 4; ++c) O[a][c] *= corr[a];

        __syncthreads();

        // O += P @ V
#pragma unroll
        for (int j = 0; j < 64; ++j) {
            float pa[4], vb[4];
            *(float4*)&pa[0] = *(const float4*)(PsT + j * P + ty * 4);
            *(float4*)&vb[0] = *(const float4*)(Vs + j * P + tx * 4);
#pragma unroll
            for (int a = 0; a < 4; ++a)
#pragma unroll
                for (int c = 0; c < 4; ++c) O[a][c] = fmaf(pa[a], vb[c], O[a][c]);
        }
    }

    // Epilogue: normalize, zero invalid query rows, write [B,N,H*DH]
#pragma unroll
    for (int a = 0; a < 4; ++a) {
        int i = ty * 4 + a;
        float mq = mask[(size_t)b * NSEQ + q0 + i];
        float inv = (mq != 0.0f) ? (1.0f / lrow[a]) : 0.0f;
        float4 v;
        v.x = O[a][0] * inv;
        v.y = O[a][1] * inv;
        v.z = O[a][2] * inv;
        v.w = O[a][3] * inv;
        *(float4*)(out + (size_t)(b * NSEQ + q0 + i) * INNER + h * DHEAD + tx * 4) = v;
    }
}

// ---------------------------------------------------------------------------
extern "C" void kernel_launch(void* const* d_in, const int* in_sizes, int n_in,
                              void* d_out, int out_size)
{
    (void)in_sizes; (void)n_in; (void)out_size;
    const float* x     = (const float*)d_in[0];  // [B,N,D]
    const float* mask  = (const float*)d_in[1];  // [B,N]
    const float* w_qkv = (const float*)d_in[2];  // [D, 3*INNER]
    const float* w_out = (const float*)d_in[3];  // [INNER, D]
    const float* b_out = (const float*)d_in[4];  // [D]
    float* out = (float*)d_out;                  // [B,N,D]

    void* p_qkv = nullptr;
    void* p_attn = nullptr;
    cudaGetSymbolAddress(&p_qkv, g_qkv);
    cudaGetSymbolAddress(&p_attn, g_attn);
    float* qkv = (float*)p_qkv;
    float* attn = (float*)p_attn;

    // 1) QKV = X @ Wqkv : [4096,1024] x [1024,3072]
    {
        dim3 grid(THREE_INNER / 128, (BDIM * NSEQ) / 128);
        sgemm_kernel<false><<<grid, 256>>>(x, w_qkv, nullptr, qkv,
                                           BDIM * NSEQ, THREE_INNER, DMODEL);
    }

    // 2) Attention
    {
        const int smem_bytes = (4 * 64 * 68 + 64) * sizeof(float);  // ~68.3 KB
        cudaFuncSetAttribute(attn_kernel,
                             cudaFuncAttributeMaxDynamicSharedMemorySize,
                             smem_bytes);
        dim3 grid(NSEQ / 64, BDIM * HEADS);
        attn_kernel<<<grid, 256, smem_bytes>>>(qkv, mask, attn);
    }

    // 3) Out = Attn @ Wout + b : [4096,1024] x [1024,1024]
    {
        dim3 grid(DMODEL / 128, (BDIM * NSEQ) / 128);
        sgemm_kernel<true><<<grid, 256>>>(attn, w_out, b_out, out,
                                          BDIM * NSEQ, DMODEL, INNER);
    }
}